// round 7
// baseline (speedup 1.0000x reference)
#include <cuda_runtime.h>

#define Bsz 64
#define Tsz 512
#define Dsz 1024
#define Usz 1024
#define NCTA 128

// Double-buffered transposed hidden state: hT[buf][k*64 + b]
__device__ __align__(16) float g_hT[2][Usz * Bsz];
__device__ volatile unsigned int g_flag[NCTA];
__device__ volatile unsigned int g_go;

// ---------------------------------------------------------------------------
// Reset scratch state so every graph replay is identical.
// ---------------------------------------------------------------------------
__global__ void init_kernel()
{
    int idx = blockIdx.x * blockDim.x + threadIdx.x;
    if (idx < Usz * Bsz) g_hT[0][idx] = 0.0f;
    if (idx < NCTA) g_flag[idx] = 0u;
    if (idx == 0) g_go = 0u;
}

// ---------------------------------------------------------------------------
// SGEMM: C[M,N] = A[M,K] * B[K,N], fp32, M=32768, N=K=1024.
// 128x128 CTA tile, BK=8, 256 threads, 8x8 register tile per thread
// (split 4+4 across tile halves for conflict-free LDS.128).
// ---------------------------------------------------------------------------
__global__ __launch_bounds__(256, 2)
void sgemm128(const float* __restrict__ A, const float* __restrict__ Bm,
              float* __restrict__ C)
{
    const int N = Usz, K = Dsz;
    __shared__ __align__(16) float As[8][128];   // transposed A tile
    __shared__ __align__(16) float Bs[8][128];

    const int tid = threadIdx.x;
    const int tx = tid & 15;        // 0..15 column group
    const int ty = tid >> 4;        // 0..15 row group
    const int row0 = blockIdx.y * 128;
    const int col0 = blockIdx.x * 128;

    const int arow = tid >> 1;            // 0..127
    const int acol = (tid & 1) << 2;      // 0 or 4
    const int brow = tid >> 5;            // 0..7
    const int bcol = (tid & 31) << 2;     // 0..124

    const float* Ap = A + (row0 + arow) * K + acol;
    const float* Bp = Bm + brow * N + col0 + bcol;

    float acc[8][8];
#pragma unroll
    for (int i = 0; i < 8; ++i)
#pragma unroll
        for (int j = 0; j < 8; ++j) acc[i][j] = 0.0f;

    for (int k0 = 0; k0 < K; k0 += 8) {
        float4 av = *(const float4*)(Ap + k0);
        float4 bv = *(const float4*)(Bp + k0 * N);
        As[acol + 0][arow] = av.x;
        As[acol + 1][arow] = av.y;
        As[acol + 2][arow] = av.z;
        As[acol + 3][arow] = av.w;
        *(float4*)&Bs[brow][bcol] = bv;
        __syncthreads();
#pragma unroll
        for (int kk = 0; kk < 8; ++kk) {
            float a[8], b[8];
            *(float4*)(a)     = *(const float4*)&As[kk][ty * 4];
            *(float4*)(a + 4) = *(const float4*)&As[kk][64 + ty * 4];
            *(float4*)(b)     = *(const float4*)&Bs[kk][tx * 4];
            *(float4*)(b + 4) = *(const float4*)&Bs[kk][64 + tx * 4];
#pragma unroll
            for (int i = 0; i < 8; ++i)
#pragma unroll
                for (int j = 0; j < 8; ++j)
                    acc[i][j] += a[i] * b[j];
        }
        __syncthreads();
    }

#pragma unroll
    for (int i = 0; i < 8; ++i) {
        int r = row0 + ((i < 4) ? (ty * 4 + i) : (64 + ty * 4 + (i - 4)));
        float4 v0 = make_float4(acc[i][0], acc[i][1], acc[i][2], acc[i][3]);
        float4 v1 = make_float4(acc[i][4], acc[i][5], acc[i][6], acc[i][7]);
        *(float4*)&C[r * N + col0 + tx * 4] = v0;
        *(float4*)&C[r * N + col0 + 64 + tx * 4] = v1;
    }
}

// ---------------------------------------------------------------------------
// Persistent recurrent kernel. 128 CTAs (one wave, co-resident), 256 threads.
// CTA owns 8 output columns for all 64 batch rows. 8 warps split K (128 each),
// 4x4 register tile per lane; smem reduction at step end; grid barrier per t.
//   out holds xk on entry; out[:,t,:] becomes h_t in place.
//   hT scratch is [k][b] transposed + double buffered for coalesced loads.
// ---------------------------------------------------------------------------
__global__ __launch_bounds__(256, 1)
void rnn_kernel(const float* __restrict__ Wr, float* __restrict__ out)
{
    __shared__ __align__(16) float Us[Usz * 8];     // this CTA's 8 U columns, 32 KB
    __shared__ __align__(16) float red[8][512];     // per-warp partials, 16 KB

    const int cta = blockIdx.x;
    const int tid = threadIdx.x;
    const int warp = tid >> 5;
    const int lane = tid & 31;
    const int c0 = cta * 8;            // column base
    const int ct = (lane & 1) << 2;    // 0 or 4   (4 columns)
    const int bt = (lane >> 1) << 2;   // 0..60    (4 batch rows)
    const int k0 = warp * 128;         // this warp's K chunk

    // Stage U[:, c0..c0+7] into smem once; reused for all 512 steps.
    for (int idx = tid; idx < Usz * 8; idx += 256) {
        int k = idx >> 3;
        int j = idx & 7;
        Us[idx] = Wr[k * Usz + c0 + j];
    }
    __syncthreads();

    for (int t = 0; t < Tsz; ++t) {
        const float* hT  = g_hT[t & 1];         // read  (zeroed for t=0)
        float*       hTn = g_hT[(t + 1) & 1];   // write

        float acc[4][4];
#pragma unroll
        for (int i = 0; i < 4; ++i)
#pragma unroll
            for (int j = 0; j < 4; ++j) acc[i][j] = 0.0f;

        const float* hp = hT + k0 * Bsz + bt;
        const float* up = Us + k0 * 8 + ct;
#pragma unroll 8
        for (int kk = 0; kk < 128; ++kk) {
            float4 hv = *(const float4*)(hp + kk * Bsz);  // h[b..b+3][k], coalesced
            float4 uv = *(const float4*)(up + kk * 8);    // U[k][c..c+3], smem
            float h4[4] = {hv.x, hv.y, hv.z, hv.w};
            float u4[4] = {uv.x, uv.y, uv.z, uv.w};
#pragma unroll
            for (int i = 0; i < 4; ++i)
#pragma unroll
                for (int j = 0; j < 4; ++j)
                    acc[i][j] += h4[i] * u4[j];
        }

        // Dump partials: red[warp][(local b)*8 + local c]
#pragma unroll
        for (int i = 0; i < 4; ++i) {
            float4 v = make_float4(acc[i][0], acc[i][1], acc[i][2], acc[i][3]);
            *(float4*)&red[warp][(bt + i) * 8 + ct] = v;
        }
        __syncthreads();

        // Reduce 8 K-partials + xk, relu, write out[:,t,:] and hT(next).
#pragma unroll
        for (int r = 0; r < 2; ++r) {
            int oi = tid * 2 + r;          // 0..511
            int lb = oi >> 3;              // batch row 0..63
            int lc = oi & 7;               // local column
            float s = red[0][oi] + red[1][oi] + red[2][oi] + red[3][oi]
                    + red[4][oi] + red[5][oi] + red[6][oi] + red[7][oi];
            int go = (lb * Tsz + t) * Usz + c0 + lc;
            float v = s + out[go];         // + xk_t
            v = fmaxf(v, 0.0f);
            out[go] = v;
            hTn[(c0 + lc) * Bsz + lb] = v;
        }

        // ---- grid barrier (flag array + master-CTA broadcast) ----
        unsigned int tv = (unsigned int)t + 1u;
        __syncthreads();
        if (tid == 0) {
            __threadfence();
            g_flag[cta] = tv;              // parallel arrives (distinct words)
        }
        if (cta == 0) {
            if (tid < NCTA) {
                while (g_flag[tid] < tv) { }
            }
            __syncthreads();
            if (tid == 0) {
                __threadfence();
                g_go = tv;                 // single release word
            }
        }
        if (tid == 0) {
            while (g_go < tv) { }
            __threadfence();
        }
        __syncthreads();
    }
}

// ---------------------------------------------------------------------------
extern "C" void kernel_launch(void* const* d_in, const int* in_sizes, int n_in,
                              void* d_out, int out_size)
{
    (void)in_sizes; (void)n_in; (void)out_size;
    const float* x  = (const float*)d_in[0];   // [64,512,1024]
    const float* W  = (const float*)d_in[1];   // [1024,1024]
    const float* Wr = (const float*)d_in[2];   // [1024,1024]
    float* out = (float*)d_out;                // [64,512,1024]

    init_kernel<<<(Usz * Bsz + 255) / 256, 256>>>();

    dim3 g(Usz / 128, (Bsz * Tsz) / 128);      // 8 x 256 CTAs
    sgemm128<<<g, 256>>>(x, W, out);           // out = x @ W  (xk)

    rnn_kernel<<<NCTA, 256>>>(Wr, out);        // sequential scan, in place
}

// round 8
// speedup vs baseline: 1.1245x; 1.1245x over previous
#include <cuda_runtime.h>

#define Bsz 64
#define Tsz 512
#define Dsz 1024
#define Usz 1024
#define NCTA 128

// Double-buffered transposed hidden state: hT[buf][k*64 + b]
__device__ __align__(16) float g_hT[2][Usz * Bsz];
__device__ volatile unsigned int g_flag[NCTA];
__device__ volatile unsigned int g_go;

// ---------------------------------------------------------------------------
// Packed fp32x2 helpers (sm_100+). Numerics identical to scalar FFMA.
// ---------------------------------------------------------------------------
__device__ __forceinline__ unsigned long long pk2(float lo, float hi)
{
    unsigned long long d;
    asm("mov.b64 %0, {%1, %2};" : "=l"(d) : "f"(lo), "f"(hi));
    return d;
}
__device__ __forceinline__ unsigned long long ffma2(unsigned long long a,
                                                    unsigned long long b,
                                                    unsigned long long c)
{
    unsigned long long d;
    asm("fma.rn.f32x2 %0, %1, %2, %3;" : "=l"(d) : "l"(a), "l"(b), "l"(c));
    return d;
}
__device__ __forceinline__ unsigned long long fadd2(unsigned long long a,
                                                    unsigned long long b)
{
    unsigned long long d;
    asm("add.rn.f32x2 %0, %1, %2;" : "=l"(d) : "l"(a), "l"(b));
    return d;
}
__device__ __forceinline__ void upk2(unsigned long long v, float& lo, float& hi)
{
    asm("mov.b64 {%0, %1}, %2;" : "=f"(lo), "=f"(hi) : "l"(v));
}

// ---------------------------------------------------------------------------
// Reset scratch state so every graph replay is identical.
// ---------------------------------------------------------------------------
__global__ void init_kernel()
{
    int idx = blockIdx.x * blockDim.x + threadIdx.x;
    if (idx < Usz * Bsz) g_hT[0][idx] = 0.0f;
    if (idx < NCTA) g_flag[idx] = 0u;
    if (idx == 0) g_go = 0u;
}

// ---------------------------------------------------------------------------
// SGEMM: C[M,N] = A[M,K] * B[K,N], fp32 via fma.rn.f32x2.
// 128x128 CTA tile, BK=8, 256 threads, 8x8 register tile per thread,
// accumulators packed over the column dimension (B pairs are naturally
// adjacent in smem; A values duplicated via mov.b64 pack on the alu pipe).
// ---------------------------------------------------------------------------
__global__ __launch_bounds__(256, 2)
void sgemm128(const float* __restrict__ A, const float* __restrict__ Bm,
              float* __restrict__ C)
{
    const int N = Usz, K = Dsz;
    __shared__ __align__(16) float As[8][128];   // transposed A tile
    __shared__ __align__(16) float Bs[8][128];

    const int tid = threadIdx.x;
    const int tx = tid & 15;        // 0..15 column group
    const int ty = tid >> 4;        // 0..15 row group
    const int row0 = blockIdx.y * 128;
    const int col0 = blockIdx.x * 128;

    const int arow = tid >> 1;            // 0..127
    const int acol = (tid & 1) << 2;      // 0 or 4
    const int brow = tid >> 5;            // 0..7
    const int bcol = (tid & 31) << 2;     // 0..124

    const float* Ap = A + (row0 + arow) * K + acol;
    const float* Bp = Bm + brow * N + col0 + bcol;

    unsigned long long acc[8][4];         // [row][colpair] packed fp32x2
#pragma unroll
    for (int i = 0; i < 8; ++i)
#pragma unroll
        for (int j = 0; j < 4; ++j) acc[i][j] = 0ull;

    for (int k0 = 0; k0 < K; k0 += 8) {
        float4 av = *(const float4*)(Ap + k0);
        float4 bv = *(const float4*)(Bp + k0 * N);
        As[acol + 0][arow] = av.x;
        As[acol + 1][arow] = av.y;
        As[acol + 2][arow] = av.z;
        As[acol + 3][arow] = av.w;
        *(float4*)&Bs[brow][bcol] = bv;
        __syncthreads();
#pragma unroll
        for (int kk = 0; kk < 8; ++kk) {
            float a[8];
            *(float4*)(a)     = *(const float4*)&As[kk][ty * 4];
            *(float4*)(a + 4) = *(const float4*)&As[kk][64 + ty * 4];
            ulonglong2 bL = *(const ulonglong2*)&Bs[kk][tx * 4];       // cols 0-3
            ulonglong2 bH = *(const ulonglong2*)&Bs[kk][64 + tx * 4];  // cols 4-7
#pragma unroll
            for (int i = 0; i < 8; ++i) {
                unsigned long long ad = pk2(a[i], a[i]);
                acc[i][0] = ffma2(ad, bL.x, acc[i][0]);
                acc[i][1] = ffma2(ad, bL.y, acc[i][1]);
                acc[i][2] = ffma2(ad, bH.x, acc[i][2]);
                acc[i][3] = ffma2(ad, bH.y, acc[i][3]);
            }
        }
        __syncthreads();
    }

#pragma unroll
    for (int i = 0; i < 8; ++i) {
        int r = row0 + ((i < 4) ? (ty * 4 + i) : (64 + ty * 4 + (i - 4)));
        ulonglong2 v0 = make_ulonglong2(acc[i][0], acc[i][1]);
        ulonglong2 v1 = make_ulonglong2(acc[i][2], acc[i][3]);
        *(ulonglong2*)&C[r * N + col0 + tx * 4] = v0;
        *(ulonglong2*)&C[r * N + col0 + 64 + tx * 4] = v1;
    }
}

// ---------------------------------------------------------------------------
// Persistent recurrent kernel, fp32x2. 128 CTAs (one wave), 256 threads.
// CTA = (column block of 16) x (batch half of 32): 64 x 2 = 128 CTAs.
// This halves L2 h-traffic vs 8col x 64b and makes each h LDG.128 a single
// 128B wavefront. 8 warps split K (128 each); lane tile 4b x 4c with
// accumulators packed over columns. Us (64KB) + red (16KB) dynamic smem.
// ---------------------------------------------------------------------------
__global__ __launch_bounds__(256, 1)
void rnn_kernel(const float* __restrict__ Wr, float* __restrict__ out)
{
    extern __shared__ char smraw[];
    float* Us  = (float*)smraw;                  // [1024][16], 64 KB
    float* red = (float*)(smraw + Usz * 16 * 4); // [8][512],   16 KB

    const int cta = blockIdx.x;
    const int tid = threadIdx.x;
    const int warp = tid >> 5;
    const int lane = tid & 31;
    const int c0 = (cta & 63) * 16;    // column base (16 cols)
    const int b0 = (cta >> 6) * 32;    // batch base  (32 rows)
    const int ct = (lane & 3) << 2;    // 0,4,8,12   (4 columns)
    const int bt = (lane >> 2) << 2;   // 0..28      (4 batch rows)
    const int k0 = warp * 128;         // this warp's K chunk

    // Stage U[:, c0..c0+15] into smem once; reused for all 512 steps.
    for (int idx = tid; idx < Usz * 16; idx += 256) {
        int k = idx >> 4;
        int j = idx & 15;
        Us[idx] = Wr[k * Usz + c0 + j];
    }
    __syncthreads();

    // Reduce-phase indices (1 packed column pair per thread, 256 pairs total)
    const int rlb = tid >> 3;          // local batch row 0..31
    const int rlc = (tid & 7) << 1;    // local column (even) 0..14

    for (int t = 0; t < Tsz; ++t) {
        const float* hT  = g_hT[t & 1];         // read  (zeroed for t=0)
        float*       hTn = g_hT[(t + 1) & 1];   // write

        // Prefetch this thread's xk pair (independent of h)
        const int go = ((b0 + rlb) * Tsz + t) * Usz + c0 + rlc;
        unsigned long long xk2 = *(const unsigned long long*)&out[go];

        unsigned long long acc[4][2];
#pragma unroll
        for (int i = 0; i < 4; ++i) { acc[i][0] = 0ull; acc[i][1] = 0ull; }

        const float* hp = hT + k0 * Bsz + b0 + bt;
        const float* up = Us + k0 * 16 + ct;
#pragma unroll 16
        for (int kk = 0; kk < 128; ++kk) {
            float4 hv = *(const float4*)(hp + kk * Bsz);          // 1 line
            ulonglong2 uv = *(const ulonglong2*)(up + kk * 16);   // smem bcast
            unsigned long long h0 = pk2(hv.x, hv.x);
            unsigned long long h1 = pk2(hv.y, hv.y);
            unsigned long long h2 = pk2(hv.z, hv.z);
            unsigned long long h3 = pk2(hv.w, hv.w);
            acc[0][0] = ffma2(h0, uv.x, acc[0][0]);
            acc[0][1] = ffma2(h0, uv.y, acc[0][1]);
            acc[1][0] = ffma2(h1, uv.x, acc[1][0]);
            acc[1][1] = ffma2(h1, uv.y, acc[1][1]);
            acc[2][0] = ffma2(h2, uv.x, acc[2][0]);
            acc[2][1] = ffma2(h2, uv.y, acc[2][1]);
            acc[3][0] = ffma2(h3, uv.x, acc[3][0]);
            acc[3][1] = ffma2(h3, uv.y, acc[3][1]);
        }

        // Dump partials: red[warp][(local b)*16 + local c], 16B stores
#pragma unroll
        for (int i = 0; i < 4; ++i) {
            *(ulonglong2*)&red[warp * 512 + (bt + i) * 16 + ct] =
                make_ulonglong2(acc[i][0], acc[i][1]);
        }
        __syncthreads();

        // Reduce 8 K-partials (packed) + xk, relu, write out and hT(next).
        {
            const int oi = tid * 2;
            unsigned long long s = *(const unsigned long long*)&red[oi];
#pragma unroll
            for (int w = 1; w < 8; ++w)
                s = fadd2(s, *(const unsigned long long*)&red[w * 512 + oi]);
            s = fadd2(s, xk2);
            float v0, v1;
            upk2(s, v0, v1);
            v0 = fmaxf(v0, 0.0f);
            v1 = fmaxf(v1, 0.0f);
            *(unsigned long long*)&out[go] = pk2(v0, v1);
            hTn[(c0 + rlc) * Bsz + b0 + rlb] = v0;
            hTn[(c0 + rlc + 1) * Bsz + b0 + rlb] = v1;
        }

        // ---- grid barrier (flag array + master-CTA broadcast) ----
        unsigned int tv = (unsigned int)t + 1u;
        __syncthreads();
        if (tid == 0) {
            __threadfence();
            g_flag[cta] = tv;              // parallel arrives (distinct words)
        }
        if (cta == 0) {
            if (tid < NCTA) {
                while (g_flag[tid] < tv) { }
            }
            __syncthreads();
            if (tid == 0) {
                __threadfence();
                g_go = tv;                 // single release word
            }
        }
        if (tid == 0) {
            while (g_go < tv) { }
            __threadfence();
        }
        __syncthreads();
    }
}

// ---------------------------------------------------------------------------
extern "C" void kernel_launch(void* const* d_in, const int* in_sizes, int n_in,
                              void* d_out, int out_size)
{
    (void)in_sizes; (void)n_in; (void)out_size;
    const float* x  = (const float*)d_in[0];   // [64,512,1024]
    const float* W  = (const float*)d_in[1];   // [1024,1024]
    const float* Wr = (const float*)d_in[2];   // [1024,1024]
    float* out = (float*)d_out;                // [64,512,1024]

    const int rnn_smem = Usz * 16 * 4 + 8 * 512 * 4;   // 80 KB dynamic
    cudaFuncSetAttribute(rnn_kernel,
                         cudaFuncAttributeMaxDynamicSharedMemorySize, rnn_smem);

    init_kernel<<<(Usz * Bsz + 255) / 256, 256>>>();

    dim3 g(Usz / 128, (Bsz * Tsz) / 128);      // 8 x 256 CTAs
    sgemm128<<<g, 256>>>(x, W, out);           // out = x @ W  (xk)

    rnn_kernel<<<NCTA, 256, rnn_smem>>>(Wr, out);   // sequential scan, in place
}